// round 7
// baseline (speedup 1.0000x reference)
#include <cuda_runtime.h>
#include <math.h>

// ---- problem dims (fixed) ----
#define B_    4
#define T_    20
#define N_    256
#define L_    (T_*N_)    // 5120
#define P_    (B_*L_)    // 20480
#define CMAP_ 2048
#define NPART 32
#define MPART 160        // 5120 / 32

typedef unsigned long long ull;

// ---- device scratch ----
__device__ float g_cm4 [4*B_*256*4];   // per-c-part vf-projected feature map
__device__ float g_abc [P_*4];         // per-query (alpha,beta,gamma,0), -log2e folded
__device__ float g_xr  [P_*2];         // per-point PE-shifted coords (xr0,xr1)
__device__ float g_part[NPART*(size_t)P_*4];  // per-part (t0,t1,t2,0)

// ---- helpers ----
__device__ __forceinline__ ull f2pack(float a, float b){ ull r; asm("mov.b64 %0,{%1,%2};":"=l"(r):"f"(a),"f"(b)); return r; }
__device__ __forceinline__ ull f2fma(ull a, ull b, ull c){ ull d; asm("fma.rn.f32x2 %0,%1,%2,%3;":"=l"(d):"l"(a),"l"(b),"l"(c)); return d; }
__device__ __forceinline__ float fex2(float x){ float r; asm("ex2.approx.f32 %0,%1;":"=f"(r):"f"(x)); return r; }
__device__ __forceinline__ float frcp(float x){ float r; asm("rcp.approx.f32 %0,%1;":"=f"(r):"f"(x)); return r; }
__device__ __forceinline__ float sigf(float x){ return 1.f/(1.f+expf(-x)); }

// ============================================================
// Kernel 1: compressor + folded vf projection (unchanged)
// ============================================================
__global__ void __launch_bounds__(256) k_compress(
    const float* __restrict__ md, const float* __restrict__ cw, const float* __restrict__ cb,
    const float* __restrict__ vf_w)
{
    __shared__ float wT[256][36];
    __shared__ float cm32[32][33];

    const int cpart = blockIdx.x & 3;
    const int tile  = (blockIdx.x >> 2) & 7;
    const int b     = blockIdx.x >> 5;
    const int tid  = threadIdx.x;
    const int lane = tid & 31;
    const int warp = tid >> 5;
    const int hw   = tile*32 + lane;

    ull acc[16];
    #pragma unroll
    for (int i=0;i<16;i++) acc[i] = 0ULL;

    #pragma unroll
    for (int chunk = 0; chunk < 2; chunk++) {
        const int cb0 = cpart*512 + chunk*256;
        __syncthreads();
        #pragma unroll 4
        for (int r = 0; r < 32; r++)
            wT[tid][r] = cw[r*CMAP_ + cb0 + tid];
        __syncthreads();

        const int cl0 = warp*32;
        #pragma unroll 4
        for (int k = 0; k < 32; k++) {
            const int cl = cl0 + k;
            float m = md[(size_t)(b*CMAP_ + cb0 + cl)*256 + hw];
            ull m2 = f2pack(m, m);
            const ulonglong2* wrow = (const ulonglong2*)(&wT[cl][0]);
            #pragma unroll
            for (int i = 0; i < 8; i++) {
                ulonglong2 wv = wrow[i];
                acc[2*i]   = f2fma(m2, wv.x, acc[2*i]);
                acc[2*i+1] = f2fma(m2, wv.y, acc[2*i+1]);
            }
        }
    }

    __syncthreads();
    {
        ull* row = (ull*)&wT[tid][0];
        #pragma unroll
        for (int i = 0; i < 16; i++) row[i] = acc[i];
    }
    __syncthreads();

    const int hwl = tid & 31;
    const int og  = tid >> 5;
    float r0=0.f, r1=0.f, r2=0.f, r3=0.f;
    #pragma unroll
    for (int w2 = 0; w2 < 8; w2++) {
        const float* rr = &wT[w2*32 + hwl][og*4];
        r0 += rr[0]; r1 += rr[1]; r2 += rr[2]; r3 += rr[3];
    }
    if (cpart == 0) {
        r0 += cb[og*4+0]; r1 += cb[og*4+1]; r2 += cb[og*4+2]; r3 += cb[og*4+3];
    }
    cm32[hwl][og*4+0] = r0; cm32[hwl][og*4+1] = r1;
    cm32[hwl][og*4+2] = r2; cm32[hwl][og*4+3] = r3;
    __syncthreads();

    if (og < 4) {
        float s = 0.f;
        #pragma unroll
        for (int j = 0; j < 32; j++)
            s = fmaf(vf_w[og*36 + 4 + j], cm32[hwl][j], s);
        g_cm4[(((size_t)cpart*B_ + b)*256 + tile*32 + hwl)*4 + og] = s;
    }
}

// ============================================================
// Kernel 2: per-point prep — now emits (xr0,xr1) and (alpha,beta,gamma)
// alpha = -log2e * Q.fc2_b ; beta = -log2e * Q.fc2_w[:,0] ; gamma = ...[:,1]
// ============================================================
__global__ void __launch_bounds__(256) k_points(
    const float* __restrict__ x,
    const float* __restrict__ w_ih, const float* __restrict__ b_ih, const float* __restrict__ b_hh,
    const float* __restrict__ vf_w, const float* __restrict__ vf_b,
    const float* __restrict__ fc_w, const float* __restrict__ fc_b,
    const float* __restrict__ fc2_w, const float* __restrict__ fc2_b)
{
    const int p = blockIdx.x*256 + threadIdx.x;
    const int b = p / L_;
    const int l = p % L_;
    const int t = l / N_;
    const int n = l % N_;

    const float x0 = x[((b*2+0)*T_ + t)*N_ + n];
    const float x1 = x[((b*2+1)*T_ + t)*N_ + n];
    const float ft = (float)t;
    const float xr0 = x0 + sinf(ft);
    const float xr1 = x1 + cosf(ft);

    // single-step LSTM (h0=c0=0)
    float X[4];
    #pragma unroll
    for (int j = 0; j < 4; j++) {
        float ig = fmaf(w_ih[2*j],      xr0, fmaf(w_ih[2*j+1],      xr1, b_ih[j]    + b_hh[j]));
        float gg = fmaf(w_ih[2*(8+j)],  xr0, fmaf(w_ih[2*(8+j)+1],  xr1, b_ih[8+j]  + b_hh[8+j]));
        float og = fmaf(w_ih[2*(12+j)], xr0, fmaf(w_ih[2*(12+j)+1], xr1, b_ih[12+j] + b_hh[12+j]));
        float c  = sigf(ig)*tanhf(gg);
        X[j] = sigf(og)*tanhf(c);
    }

    // bilinear sample of projected maps
    const float ix = x0*(1.f/32.f) - 0.5f;
    const float iy = x1*(1.f/32.f) - 0.5f;
    const float x0f = floorf(ix), y0f = floorf(iy);
    const float wx1 = ix - x0f, wx0 = 1.f - wx1;
    const float wy1 = iy - y0f, wy0 = 1.f - wy1;
    const int xi0 = (int)x0f, yi0 = (int)y0f;

    float lcp0=0.f, lcp1=0.f, lcp2=0.f, lcp3=0.f;
    #pragma unroll
    for (int cy = 0; cy < 2; cy++) {
        #pragma unroll
        for (int cx = 0; cx < 2; cx++) {
            const int xi = xi0 + cx, yi = yi0 + cy;
            const float wgt = (cx ? wx1 : wx0) * (cy ? wy1 : wy0);
            if (xi >= 0 && xi < 16 && yi >= 0 && yi < 16) {
                #pragma unroll
                for (int part = 0; part < 4; part++) {
                    float4 v = *(const float4*)&g_cm4[(((size_t)part*B_ + b)*256 + yi*16 + xi)*4];
                    lcp0 = fmaf(wgt, v.x, lcp0);
                    lcp1 = fmaf(wgt, v.y, lcp1);
                    lcp2 = fmaf(wgt, v.z, lcp2);
                    lcp3 = fmaf(wgt, v.w, lcp3);
                }
            }
        }
    }

    float X2[4];
    {
        float lcp[4] = {lcp0, lcp1, lcp2, lcp3};
        #pragma unroll
        for (int i = 0; i < 4; i++) {
            float s = vf_b[i] + lcp[i];
            #pragma unroll
            for (int j = 0; j < 4; j++) s = fmaf(vf_w[i*36+j], X[j], s);
            X2[i] = s;
        }
    }

    // Q then collapse against the rank-2 K factorization
    float alpha = 0.f, beta = 0.f, gamma = 0.f;
    #pragma unroll
    for (int k = 0; k < 8; k++) {
        float q = fc_b[k];
        #pragma unroll
        for (int i = 0; i < 4; i++) q = fmaf(fc_w[k*4+i], X2[i], q);
        alpha = fmaf(q, fc2_b[k],    alpha);
        beta  = fmaf(q, fc2_w[2*k],  beta);
        gamma = fmaf(q, fc2_w[2*k+1],gamma);
    }
    const float NEGL2E = -1.4426950408889634f;
    float4 abc; abc.x = alpha*NEGL2E; abc.y = beta*NEGL2E; abc.z = gamma*NEGL2E; abc.w = 0.f;
    *(float4*)&g_abc[(size_t)p*4] = abc;
    float2 xr; xr.x = xr0; xr.y = xr1;
    *(float2*)&g_xr[(size_t)p*2] = xr;
}

// ============================================================
// Kernel 3: attention partials — rank-collapsed
// per (query, part): t0 = sum s, t1 = sum s*x0, t2 = sum s*x1
// grid (5 l-tiles, 32 m-parts, 4 batches) = 640 blocks, 256 threads, 4 q/thread
// ============================================================
__global__ void __launch_bounds__(256) k_attn()
{
    __shared__ float4 sxr[MPART/2];   // 160 keys -> 80 float4 (x0a,x1a,x0b,x1b)

    const int b  = blockIdx.z;
    const int mp = blockIdx.y;
    const int lb = blockIdx.x*1024 + threadIdx.x;

    if (threadIdx.x < MPART/2)
        sxr[threadIdx.x] = ((const float4*)(g_xr + ((size_t)b*L_ + (size_t)mp*MPART)*2))[threadIdx.x];

    float al[4], be[4], ga[4];
    #pragma unroll
    for (int j = 0; j < 4; j++) {
        float4 abc = *(const float4*)&g_abc[((size_t)b*L_ + lb + j*256)*4];
        al[j] = abc.x; be[j] = abc.y; ga[j] = abc.z;
    }
    __syncthreads();

    float t0[4], t1[4], t2[4];
    #pragma unroll
    for (int j = 0; j < 4; j++) { t0[j]=0.f; t1[j]=0.f; t2[j]=0.f; }

    #pragma unroll 2
    for (int mm = 0; mm < MPART/2; mm++) {
        float4 xv = sxr[mm];   // two keys, broadcast LDS.128
        #pragma unroll
        for (int j = 0; j < 4; j++) {
            float za = fmaf(be[j], xv.x, fmaf(ga[j], xv.y, al[j]));
            float sa = frcp(1.f + fex2(za));
            t0[j] += sa;
            t1[j]  = fmaf(sa, xv.x, t1[j]);
            t2[j]  = fmaf(sa, xv.y, t2[j]);
            float zb = fmaf(be[j], xv.z, fmaf(ga[j], xv.w, al[j]));
            float sb = frcp(1.f + fex2(zb));
            t0[j] += sb;
            t1[j]  = fmaf(sb, xv.z, t1[j]);
            t2[j]  = fmaf(sb, xv.w, t2[j]);
        }
    }

    #pragma unroll
    for (int j = 0; j < 4; j++) {
        float4 w; w.x = t0[j]; w.y = t1[j]; w.z = t2[j]; w.w = 0.f;
        *(float4*)&g_part[((size_t)mp*P_ + (size_t)b*L_ + lb + j*256)*4] = w;
    }
}

// ============================================================
// Kernel 4: combine + rank-3 V reconstruct + threshold + fco -> out
// 4 threads per query, each sums 8 parts, shfl-reduce, lane sub==0 writes
// ============================================================
__global__ void __launch_bounds__(256) k_combine(
    const float* __restrict__ fc3_w, const float* __restrict__ fc3_b,
    const float* __restrict__ fco_w, const float* __restrict__ fco_b,
    float* __restrict__ out)
{
    const int idx = blockIdx.x*256 + threadIdx.x;
    const int p   = idx >> 2;
    const int sub = idx & 3;

    float t0=0.f, t1=0.f, t2=0.f;
    #pragma unroll
    for (int i = 0; i < NPART/4; i++) {
        const int s = sub*(NPART/4) + i;
        float4 a = *(const float4*)&g_part[((size_t)s*P_ + p)*4];
        t0 += a.x; t1 += a.y; t2 += a.z;
    }
    t0 += __shfl_xor_sync(0xffffffffu, t0, 1);
    t1 += __shfl_xor_sync(0xffffffffu, t1, 1);
    t2 += __shfl_xor_sync(0xffffffffu, t2, 1);
    t0 += __shfl_xor_sync(0xffffffffu, t0, 2);
    t1 += __shfl_xor_sync(0xffffffffu, t1, 2);
    t2 += __shfl_xor_sync(0xffffffffu, t2, 2);

    if (sub == 0) {
        float r0 = fco_b[0], r1 = fco_b[1];
        #pragma unroll
        for (int i = 0; i < 8; i++) {
            float o = fmaf(t0, fc3_b[i], fmaf(t1, fc3_w[2*i], t2*fc3_w[2*i+1]));
            o = (o > 0.5f) ? o : 0.f;
            r0 = fmaf(fco_w[i],   o, r0);
            r1 = fmaf(fco_w[8+i], o, r1);
        }
        const int b = p / L_;
        const int l = p % L_;
        const int t = l / N_;
        const int n = l % N_;
        out[((b*2+0)*T_ + t)*N_ + n] = r0;
        out[((b*2+1)*T_ + t)*N_ + n] = r1;
    }
}

// ============================================================
extern "C" void kernel_launch(void* const* d_in, const int* in_sizes, int n_in,
                              void* d_out, int out_size)
{
    const float* x      = (const float*)d_in[0];
    const float* md     = (const float*)d_in[1];
    const float* w_ih   = (const float*)d_in[2];
    const float* b_ih   = (const float*)d_in[3];
    const float* b_hh   = (const float*)d_in[4];
    const float* comp_w = (const float*)d_in[5];
    const float* comp_b = (const float*)d_in[6];
    const float* vf_w   = (const float*)d_in[7];
    const float* vf_b   = (const float*)d_in[8];
    const float* fc_w   = (const float*)d_in[9];
    const float* fc_b   = (const float*)d_in[10];
    const float* fc2_w  = (const float*)d_in[11];
    const float* fc2_b  = (const float*)d_in[12];
    const float* fc3_w  = (const float*)d_in[13];
    const float* fc3_b  = (const float*)d_in[14];
    const float* fco_w  = (const float*)d_in[15];
    const float* fco_b  = (const float*)d_in[16];
    float* out = (float*)d_out;

    k_compress<<<128, 256>>>(md, comp_w, comp_b, vf_w);
    k_points<<<P_/256, 256>>>(x, w_ih, b_ih, b_hh, vf_w, vf_b,
                              fc_w, fc_b, fc2_w, fc2_b);
    k_attn<<<dim3(L_/1024, NPART, B_), 256>>>();
    k_combine<<<(P_*4)/256, 256>>>(fc3_w, fc3_b, fco_w, fco_b, out);
}

// round 8
// speedup vs baseline: 1.2068x; 1.2068x over previous
#include <cuda_runtime.h>
#include <math.h>

// ---- problem dims (fixed) ----
#define B_    4
#define T_    20
#define N_    256
#define L_    (T_*N_)    // 5120
#define P_    (B_*L_)    // 20480
#define CMAP_ 2048
#define NPART 16
#define MPART 320        // 5120 / 16

typedef unsigned long long ull;

// ---- device scratch ----
__device__ float g_cm4 [4*B_*256*4];   // per-c-part vf-projected feature map
__device__ float g_abc [P_*4];         // per-query (alpha,beta,gamma,0), 0.5 folded (tanh arg)
__device__ float g_xr  [P_*2];         // per-point PE-shifted coords (xr0,xr1)
__device__ float g_part[NPART*(size_t)P_*4];  // per-part (u0,u1,u2,0) tau-sums
__device__ float g_S   [B_*2];         // per-batch (sum xr0, sum xr1)

// ---- helpers ----
__device__ __forceinline__ ull f2pack(float a, float b){ ull r; asm("mov.b64 %0,{%1,%2};":"=l"(r):"f"(a),"f"(b)); return r; }
__device__ __forceinline__ ull f2fma(ull a, ull b, ull c){ ull d; asm("fma.rn.f32x2 %0,%1,%2,%3;":"=l"(d):"l"(a),"l"(b),"l"(c)); return d; }
__device__ __forceinline__ float ftanh(float x){ float r; asm("tanh.approx.f32 %0,%1;":"=f"(r):"f"(x)); return r; }
__device__ __forceinline__ float sigf(float x){ return 1.f/(1.f+expf(-x)); }  // precise path (k_points only)

// ============================================================
// Kernel 1: compressor + folded vf projection
// ============================================================
__global__ void __launch_bounds__(256) k_compress(
    const float* __restrict__ md, const float* __restrict__ cw, const float* __restrict__ cb,
    const float* __restrict__ vf_w)
{
    __shared__ float wT[256][36];
    __shared__ float cm32[32][33];

    const int cpart = blockIdx.x & 3;
    const int tile  = (blockIdx.x >> 2) & 7;
    const int b     = blockIdx.x >> 5;
    const int tid  = threadIdx.x;
    const int lane = tid & 31;
    const int warp = tid >> 5;
    const int hw   = tile*32 + lane;

    ull acc[16];
    #pragma unroll
    for (int i=0;i<16;i++) acc[i] = 0ULL;

    #pragma unroll
    for (int chunk = 0; chunk < 2; chunk++) {
        const int cb0 = cpart*512 + chunk*256;
        __syncthreads();
        #pragma unroll 4
        for (int r = 0; r < 32; r++)
            wT[tid][r] = cw[r*CMAP_ + cb0 + tid];
        __syncthreads();

        const int cl0 = warp*32;
        #pragma unroll 4
        for (int k = 0; k < 32; k++) {
            const int cl = cl0 + k;
            float m = md[(size_t)(b*CMAP_ + cb0 + cl)*256 + hw];
            ull m2 = f2pack(m, m);
            const ulonglong2* wrow = (const ulonglong2*)(&wT[cl][0]);
            #pragma unroll
            for (int i = 0; i < 8; i++) {
                ulonglong2 wv = wrow[i];
                acc[2*i]   = f2fma(m2, wv.x, acc[2*i]);
                acc[2*i+1] = f2fma(m2, wv.y, acc[2*i+1]);
            }
        }
    }

    __syncthreads();
    {
        ull* row = (ull*)&wT[tid][0];
        #pragma unroll
        for (int i = 0; i < 16; i++) row[i] = acc[i];
    }
    __syncthreads();

    const int hwl = tid & 31;
    const int og  = tid >> 5;
    float r0=0.f, r1=0.f, r2=0.f, r3=0.f;
    #pragma unroll
    for (int w2 = 0; w2 < 8; w2++) {
        const float* rr = &wT[w2*32 + hwl][og*4];
        r0 += rr[0]; r1 += rr[1]; r2 += rr[2]; r3 += rr[3];
    }
    if (cpart == 0) {
        r0 += cb[og*4+0]; r1 += cb[og*4+1]; r2 += cb[og*4+2]; r3 += cb[og*4+3];
    }
    cm32[hwl][og*4+0] = r0; cm32[hwl][og*4+1] = r1;
    cm32[hwl][og*4+2] = r2; cm32[hwl][og*4+3] = r3;
    __syncthreads();

    if (og < 4) {
        float s = 0.f;
        #pragma unroll
        for (int j = 0; j < 32; j++)
            s = fmaf(vf_w[og*36 + 4 + j], cm32[hwl][j], s);
        g_cm4[(((size_t)cpart*B_ + b)*256 + tile*32 + hwl)*4 + og] = s;
    }
}

// ============================================================
// Kernel 2: per-point prep — emits (xr0,xr1) and (alpha,beta,gamma)*0.5
// ============================================================
__global__ void __launch_bounds__(256) k_points(
    const float* __restrict__ x,
    const float* __restrict__ w_ih, const float* __restrict__ b_ih, const float* __restrict__ b_hh,
    const float* __restrict__ vf_w, const float* __restrict__ vf_b,
    const float* __restrict__ fc_w, const float* __restrict__ fc_b,
    const float* __restrict__ fc2_w, const float* __restrict__ fc2_b)
{
    const int p = blockIdx.x*256 + threadIdx.x;
    const int b = p / L_;
    const int l = p % L_;
    const int t = l / N_;
    const int n = l % N_;

    const float x0 = x[((b*2+0)*T_ + t)*N_ + n];
    const float x1 = x[((b*2+1)*T_ + t)*N_ + n];
    const float ft = (float)t;
    const float xr0 = x0 + sinf(ft);
    const float xr1 = x1 + cosf(ft);

    // single-step LSTM (h0=c0=0)
    float X[4];
    #pragma unroll
    for (int j = 0; j < 4; j++) {
        float ig = fmaf(w_ih[2*j],      xr0, fmaf(w_ih[2*j+1],      xr1, b_ih[j]    + b_hh[j]));
        float gg = fmaf(w_ih[2*(8+j)],  xr0, fmaf(w_ih[2*(8+j)+1],  xr1, b_ih[8+j]  + b_hh[8+j]));
        float og = fmaf(w_ih[2*(12+j)], xr0, fmaf(w_ih[2*(12+j)+1], xr1, b_ih[12+j] + b_hh[12+j]));
        float c  = sigf(ig)*tanhf(gg);
        X[j] = sigf(og)*tanhf(c);
    }

    // bilinear sample of projected maps
    const float ix = x0*(1.f/32.f) - 0.5f;
    const float iy = x1*(1.f/32.f) - 0.5f;
    const float x0f = floorf(ix), y0f = floorf(iy);
    const float wx1 = ix - x0f, wx0 = 1.f - wx1;
    const float wy1 = iy - y0f, wy0 = 1.f - wy1;
    const int xi0 = (int)x0f, yi0 = (int)y0f;

    float lcp0=0.f, lcp1=0.f, lcp2=0.f, lcp3=0.f;
    #pragma unroll
    for (int cy = 0; cy < 2; cy++) {
        #pragma unroll
        for (int cx = 0; cx < 2; cx++) {
            const int xi = xi0 + cx, yi = yi0 + cy;
            const float wgt = (cx ? wx1 : wx0) * (cy ? wy1 : wy0);
            if (xi >= 0 && xi < 16 && yi >= 0 && yi < 16) {
                #pragma unroll
                for (int part = 0; part < 4; part++) {
                    float4 v = *(const float4*)&g_cm4[(((size_t)part*B_ + b)*256 + yi*16 + xi)*4];
                    lcp0 = fmaf(wgt, v.x, lcp0);
                    lcp1 = fmaf(wgt, v.y, lcp1);
                    lcp2 = fmaf(wgt, v.z, lcp2);
                    lcp3 = fmaf(wgt, v.w, lcp3);
                }
            }
        }
    }

    float X2[4];
    {
        float lcp[4] = {lcp0, lcp1, lcp2, lcp3};
        #pragma unroll
        for (int i = 0; i < 4; i++) {
            float s = vf_b[i] + lcp[i];
            #pragma unroll
            for (int j = 0; j < 4; j++) s = fmaf(vf_w[i*36+j], X[j], s);
            X2[i] = s;
        }
    }

    // Q then collapse against the rank-2 K factorization; 0.5 folded for tanh arg
    float alpha = 0.f, beta = 0.f, gamma = 0.f;
    #pragma unroll
    for (int k = 0; k < 8; k++) {
        float q = fc_b[k];
        #pragma unroll
        for (int i = 0; i < 4; i++) q = fmaf(fc_w[k*4+i], X2[i], q);
        alpha = fmaf(q, fc2_b[k],    alpha);
        beta  = fmaf(q, fc2_w[2*k],  beta);
        gamma = fmaf(q, fc2_w[2*k+1],gamma);
    }
    float4 abc; abc.x = alpha*0.5f; abc.y = beta*0.5f; abc.z = gamma*0.5f; abc.w = 0.f;
    *(float4*)&g_abc[(size_t)p*4] = abc;
    float2 xr; xr.x = xr0; xr.y = xr1;
    *(float2*)&g_xr[(size_t)p*2] = xr;
}

// ============================================================
// Kernel 2b: per-batch key coordinate sums (deterministic tree reduce)
// ============================================================
__global__ void __launch_bounds__(256) k_keysum()
{
    __shared__ float r0[256], r1[256];
    const int b   = blockIdx.x;
    const int tid = threadIdx.x;

    float s0 = 0.f, s1 = 0.f;
    for (int i = tid; i < L_; i += 256) {
        float2 v = ((const float2*)g_xr)[(size_t)b*L_ + i];
        s0 += v.x; s1 += v.y;
    }
    r0[tid] = s0; r1[tid] = s1;
    __syncthreads();
    #pragma unroll
    for (int off = 128; off > 0; off >>= 1) {
        if (tid < off) { r0[tid] += r0[tid+off]; r1[tid] += r1[tid+off]; }
        __syncthreads();
    }
    if (tid == 0) { g_S[b*2] = r0[0]; g_S[b*2+1] = r1[0]; }
}

// ============================================================
// Kernel 3: attention partials — tanh form, 1 MUFU per pair
// u0 = sum tau, u1 = sum tau*x0, u2 = sum tau*x1
// grid (5 l-tiles, 16 m-parts, 4 batches) = 320 blocks, 256 thr, 4 q/thread
// ============================================================
__global__ void __launch_bounds__(256) k_attn()
{
    __shared__ float4 sxr[MPART/2];   // 320 keys -> 160 float4 (x0a,x1a,x0b,x1b)

    const int b  = blockIdx.z;
    const int mp = blockIdx.y;
    const int lb = blockIdx.x*1024 + threadIdx.x;

    if (threadIdx.x < MPART/2)
        sxr[threadIdx.x] = ((const float4*)(g_xr + ((size_t)b*L_ + (size_t)mp*MPART)*2))[threadIdx.x];

    float al[4], be[4], ga[4];
    #pragma unroll
    for (int j = 0; j < 4; j++) {
        float4 abc = *(const float4*)&g_abc[((size_t)b*L_ + lb + j*256)*4];
        al[j] = abc.x; be[j] = abc.y; ga[j] = abc.z;
    }
    __syncthreads();

    float u0[4], u1[4], u2[4];
    #pragma unroll
    for (int j = 0; j < 4; j++) { u0[j]=0.f; u1[j]=0.f; u2[j]=0.f; }

    #pragma unroll 2
    for (int mm = 0; mm < MPART/2; mm++) {
        float4 xv = sxr[mm];   // two keys, broadcast LDS.128
        #pragma unroll
        for (int j = 0; j < 4; j++) {
            float za = fmaf(be[j], xv.x, fmaf(ga[j], xv.y, al[j]));
            float ta = ftanh(za);
            u0[j] += ta;
            u1[j]  = fmaf(ta, xv.x, u1[j]);
            u2[j]  = fmaf(ta, xv.y, u2[j]);
            float zb = fmaf(be[j], xv.z, fmaf(ga[j], xv.w, al[j]));
            float tb = ftanh(zb);
            u0[j] += tb;
            u1[j]  = fmaf(tb, xv.z, u1[j]);
            u2[j]  = fmaf(tb, xv.w, u2[j]);
        }
    }

    #pragma unroll
    for (int j = 0; j < 4; j++) {
        float4 w; w.x = u0[j]; w.y = u1[j]; w.z = u2[j]; w.w = 0.f;
        *(float4*)&g_part[((size_t)mp*P_ + (size_t)b*L_ + lb + j*256)*4] = w;
    }
}

// ============================================================
// Kernel 4: combine + sigmoid restore + rank-3 V + threshold + fco -> out
// t = 0.5*(sum u + S); 4 threads/query, shfl reduce
// ============================================================
__global__ void __launch_bounds__(256) k_combine(
    const float* __restrict__ fc3_w, const float* __restrict__ fc3_b,
    const float* __restrict__ fco_w, const float* __restrict__ fco_b,
    float* __restrict__ out)
{
    const int idx = blockIdx.x*256 + threadIdx.x;
    const int p   = idx >> 2;
    const int sub = idx & 3;

    float u0=0.f, u1=0.f, u2=0.f;
    #pragma unroll
    for (int i = 0; i < NPART/4; i++) {
        const int s = sub*(NPART/4) + i;
        float4 a = *(const float4*)&g_part[((size_t)s*P_ + p)*4];
        u0 += a.x; u1 += a.y; u2 += a.z;
    }
    u0 += __shfl_xor_sync(0xffffffffu, u0, 1);
    u1 += __shfl_xor_sync(0xffffffffu, u1, 1);
    u2 += __shfl_xor_sync(0xffffffffu, u2, 1);
    u0 += __shfl_xor_sync(0xffffffffu, u0, 2);
    u1 += __shfl_xor_sync(0xffffffffu, u1, 2);
    u2 += __shfl_xor_sync(0xffffffffu, u2, 2);

    if (sub == 0) {
        const int b = p / L_;
        const float t0 = 0.5f*(u0 + (float)L_);
        const float t1 = 0.5f*(u1 + g_S[b*2]);
        const float t2 = 0.5f*(u2 + g_S[b*2+1]);

        float r0 = fco_b[0], r1 = fco_b[1];
        #pragma unroll
        for (int i = 0; i < 8; i++) {
            float o = fmaf(t0, fc3_b[i], fmaf(t1, fc3_w[2*i], t2*fc3_w[2*i+1]));
            o = (o > 0.5f) ? o : 0.f;
            r0 = fmaf(fco_w[i],   o, r0);
            r1 = fmaf(fco_w[8+i], o, r1);
        }
        const int l = p % L_;
        const int t = l / N_;
        const int n = l % N_;
        out[((b*2+0)*T_ + t)*N_ + n] = r0;
        out[((b*2+1)*T_ + t)*N_ + n] = r1;
    }
}

// ============================================================
extern "C" void kernel_launch(void* const* d_in, const int* in_sizes, int n_in,
                              void* d_out, int out_size)
{
    const float* x      = (const float*)d_in[0];
    const float* md     = (const float*)d_in[1];
    const float* w_ih   = (const float*)d_in[2];
    const float* b_ih   = (const float*)d_in[3];
    const float* b_hh   = (const float*)d_in[4];
    const float* comp_w = (const float*)d_in[5];
    const float* comp_b = (const float*)d_in[6];
    const float* vf_w   = (const float*)d_in[7];
    const float* vf_b   = (const float*)d_in[8];
    const float* fc_w   = (const float*)d_in[9];
    const float* fc_b   = (const float*)d_in[10];
    const float* fc2_w  = (const float*)d_in[11];
    const float* fc2_b  = (const float*)d_in[12];
    const float* fco_w  = (const float*)d_in[15];
    const float* fco_b  = (const float*)d_in[16];
    const float* fc3_w  = (const float*)d_in[13];
    const float* fc3_b  = (const float*)d_in[14];
    float* out = (float*)d_out;

    k_compress<<<128, 256>>>(md, comp_w, comp_b, vf_w);
    k_points<<<P_/256, 256>>>(x, w_ih, b_ih, b_hh, vf_w, vf_b,
                              fc_w, fc_b, fc2_w, fc2_b);
    k_keysum<<<B_, 256>>>();
    k_attn<<<dim3(L_/1024, NPART, B_), 256>>>();
    k_combine<<<(P_*4)/256, 256>>>(fc3_w, fc3_b, fco_w, fco_b, out);
}

// round 9
// speedup vs baseline: 1.4965x; 1.2401x over previous
#include <cuda_runtime.h>
#include <math.h>

// ---- problem dims (fixed) ----
#define B_    4
#define T_    20
#define N_    256
#define L_    (T_*N_)    // 5120
#define P_    (B_*L_)    // 20480
#define CMAP_ 2048
#define NPART 37         // 5 l-tiles * 37 * 4 batches = 740 = 148 SMs * 5 exactly
#define MPBASE 138       // 5120 = 14*139 + 23*138
#define MPREM  14
#define KSLICE 8         // keysum slices per batch

typedef unsigned long long ull;

// ---- device scratch ----
__device__ float g_cm4 [4*B_*256*4];
__device__ float g_abc [P_*4];
__device__ float g_xr  [P_*2];
__device__ float g_part[NPART*(size_t)P_*4];
__device__ float g_Sp  [B_*KSLICE*2];     // partial key-coord sums

// ---- helpers ----
__device__ __forceinline__ ull f2pack(float a, float b){ ull r; asm("mov.b64 %0,{%1,%2};":"=l"(r):"f"(a),"f"(b)); return r; }
__device__ __forceinline__ ull f2fma(ull a, ull b, ull c){ ull d; asm("fma.rn.f32x2 %0,%1,%2,%3;":"=l"(d):"l"(a),"l"(b),"l"(c)); return d; }
__device__ __forceinline__ float ftanh(float x){ float r; asm("tanh.approx.f32 %0,%1;":"=f"(r):"f"(x)); return r; }
__device__ __forceinline__ float sigf(float x){ return 1.f/(1.f+expf(-x)); }

// part s start offset and length
__device__ __forceinline__ int part_start(int s){ return s*MPBASE + (s < MPREM ? s : MPREM); }
__device__ __forceinline__ int part_len(int s){ return MPBASE + (s < MPREM ? 1 : 0); }

// ============================================================
// Kernel 1: compressor + folded vf projection
// ============================================================
__global__ void __launch_bounds__(256) k_compress(
    const float* __restrict__ md, const float* __restrict__ cw, const float* __restrict__ cb,
    const float* __restrict__ vf_w)
{
    __shared__ float wT[256][36];
    __shared__ float cm32[32][33];

    const int cpart = blockIdx.x & 3;
    const int tile  = (blockIdx.x >> 2) & 7;
    const int b     = blockIdx.x >> 5;
    const int tid  = threadIdx.x;
    const int lane = tid & 31;
    const int warp = tid >> 5;
    const int hw   = tile*32 + lane;

    ull acc[16];
    #pragma unroll
    for (int i=0;i<16;i++) acc[i] = 0ULL;

    #pragma unroll
    for (int chunk = 0; chunk < 2; chunk++) {
        const int cb0 = cpart*512 + chunk*256;
        __syncthreads();
        #pragma unroll 4
        for (int r = 0; r < 32; r++)
            wT[tid][r] = cw[r*CMAP_ + cb0 + tid];
        __syncthreads();

        const int cl0 = warp*32;
        #pragma unroll 4
        for (int k = 0; k < 32; k++) {
            const int cl = cl0 + k;
            float m = md[(size_t)(b*CMAP_ + cb0 + cl)*256 + hw];
            ull m2 = f2pack(m, m);
            const ulonglong2* wrow = (const ulonglong2*)(&wT[cl][0]);
            #pragma unroll
            for (int i = 0; i < 8; i++) {
                ulonglong2 wv = wrow[i];
                acc[2*i]   = f2fma(m2, wv.x, acc[2*i]);
                acc[2*i+1] = f2fma(m2, wv.y, acc[2*i+1]);
            }
        }
    }

    __syncthreads();
    {
        ull* row = (ull*)&wT[tid][0];
        #pragma unroll
        for (int i = 0; i < 16; i++) row[i] = acc[i];
    }
    __syncthreads();

    const int hwl = tid & 31;
    const int og  = tid >> 5;
    float r0=0.f, r1=0.f, r2=0.f, r3=0.f;
    #pragma unroll
    for (int w2 = 0; w2 < 8; w2++) {
        const float* rr = &wT[w2*32 + hwl][og*4];
        r0 += rr[0]; r1 += rr[1]; r2 += rr[2]; r3 += rr[3];
    }
    if (cpart == 0) {
        r0 += cb[og*4+0]; r1 += cb[og*4+1]; r2 += cb[og*4+2]; r3 += cb[og*4+3];
    }
    cm32[hwl][og*4+0] = r0; cm32[hwl][og*4+1] = r1;
    cm32[hwl][og*4+2] = r2; cm32[hwl][og*4+3] = r3;
    __syncthreads();

    if (og < 4) {
        float s = 0.f;
        #pragma unroll
        for (int j = 0; j < 32; j++)
            s = fmaf(vf_w[og*36 + 4 + j], cm32[hwl][j], s);
        g_cm4[(((size_t)cpart*B_ + b)*256 + tile*32 + hwl)*4 + og] = s;
    }
}

// ============================================================
// Kernel 2: per-point prep — emits (xr0,xr1) and 0.5*(alpha,beta,gamma)
// ============================================================
__global__ void __launch_bounds__(256) k_points(
    const float* __restrict__ x,
    const float* __restrict__ w_ih, const float* __restrict__ b_ih, const float* __restrict__ b_hh,
    const float* __restrict__ vf_w, const float* __restrict__ vf_b,
    const float* __restrict__ fc_w, const float* __restrict__ fc_b,
    const float* __restrict__ fc2_w, const float* __restrict__ fc2_b)
{
    const int p = blockIdx.x*256 + threadIdx.x;
    const int b = p / L_;
    const int l = p % L_;
    const int t = l / N_;
    const int n = l % N_;

    const float x0 = x[((b*2+0)*T_ + t)*N_ + n];
    const float x1 = x[((b*2+1)*T_ + t)*N_ + n];
    const float ft = (float)t;
    const float xr0 = x0 + sinf(ft);
    const float xr1 = x1 + cosf(ft);

    float X[4];
    #pragma unroll
    for (int j = 0; j < 4; j++) {
        float ig = fmaf(w_ih[2*j],      xr0, fmaf(w_ih[2*j+1],      xr1, b_ih[j]    + b_hh[j]));
        float gg = fmaf(w_ih[2*(8+j)],  xr0, fmaf(w_ih[2*(8+j)+1],  xr1, b_ih[8+j]  + b_hh[8+j]));
        float og = fmaf(w_ih[2*(12+j)], xr0, fmaf(w_ih[2*(12+j)+1], xr1, b_ih[12+j] + b_hh[12+j]));
        float c  = sigf(ig)*tanhf(gg);
        X[j] = sigf(og)*tanhf(c);
    }

    const float ix = x0*(1.f/32.f) - 0.5f;
    const float iy = x1*(1.f/32.f) - 0.5f;
    const float x0f = floorf(ix), y0f = floorf(iy);
    const float wx1 = ix - x0f, wx0 = 1.f - wx1;
    const float wy1 = iy - y0f, wy0 = 1.f - wy1;
    const int xi0 = (int)x0f, yi0 = (int)y0f;

    float lcp0=0.f, lcp1=0.f, lcp2=0.f, lcp3=0.f;
    #pragma unroll
    for (int cy = 0; cy < 2; cy++) {
        #pragma unroll
        for (int cx = 0; cx < 2; cx++) {
            const int xi = xi0 + cx, yi = yi0 + cy;
            const float wgt = (cx ? wx1 : wx0) * (cy ? wy1 : wy0);
            if (xi >= 0 && xi < 16 && yi >= 0 && yi < 16) {
                #pragma unroll
                for (int part = 0; part < 4; part++) {
                    float4 v = *(const float4*)&g_cm4[(((size_t)part*B_ + b)*256 + yi*16 + xi)*4];
                    lcp0 = fmaf(wgt, v.x, lcp0);
                    lcp1 = fmaf(wgt, v.y, lcp1);
                    lcp2 = fmaf(wgt, v.z, lcp2);
                    lcp3 = fmaf(wgt, v.w, lcp3);
                }
            }
        }
    }

    float X2[4];
    {
        float lcp[4] = {lcp0, lcp1, lcp2, lcp3};
        #pragma unroll
        for (int i = 0; i < 4; i++) {
            float s = vf_b[i] + lcp[i];
            #pragma unroll
            for (int j = 0; j < 4; j++) s = fmaf(vf_w[i*36+j], X[j], s);
            X2[i] = s;
        }
    }

    float alpha = 0.f, beta = 0.f, gamma = 0.f;
    #pragma unroll
    for (int k = 0; k < 8; k++) {
        float q = fc_b[k];
        #pragma unroll
        for (int i = 0; i < 4; i++) q = fmaf(fc_w[k*4+i], X2[i], q);
        alpha = fmaf(q, fc2_b[k],    alpha);
        beta  = fmaf(q, fc2_w[2*k],  beta);
        gamma = fmaf(q, fc2_w[2*k+1],gamma);
    }
    float4 abc; abc.x = alpha*0.5f; abc.y = beta*0.5f; abc.z = gamma*0.5f; abc.w = 0.f;
    *(float4*)&g_abc[(size_t)p*4] = abc;
    float2 xr; xr.x = xr0; xr.y = xr1;
    *(float2*)&g_xr[(size_t)p*2] = xr;
}

// ============================================================
// Kernel 2b: per-batch key coord partial sums — 32 blocks (b x 8 slices)
// ============================================================
__global__ void __launch_bounds__(256) k_keysum()
{
    __shared__ float r0[256], r1[256];
    const int b     = blockIdx.x >> 3;
    const int slice = blockIdx.x & 7;
    const int tid   = threadIdx.x;
    const int SLEN  = L_/KSLICE;   // 640

    float s0 = 0.f, s1 = 0.f;
    #pragma unroll
    for (int i = 0; i < SLEN/256 + 1; i++) {
        int k = i*256 + tid;
        if (k < SLEN) {
            float2 v = ((const float2*)g_xr)[(size_t)b*L_ + slice*SLEN + k];
            s0 += v.x; s1 += v.y;
        }
    }
    r0[tid] = s0; r1[tid] = s1;
    __syncthreads();
    #pragma unroll
    for (int off = 128; off > 0; off >>= 1) {
        if (tid < off) { r0[tid] += r0[tid+off]; r1[tid] += r1[tid+off]; }
        __syncthreads();
    }
    if (tid == 0) {
        g_Sp[(b*KSLICE + slice)*2]     = r0[0];
        g_Sp[(b*KSLICE + slice)*2 + 1] = r1[0];
    }
}

// ============================================================
// Kernel 3: attention partials — tanh form, balanced 740-block grid
// grid (5 l-tiles, 37 m-parts, 4 batches) = 740 = 148*5, 256 thr, 4 q/thr
// ============================================================
__global__ void __launch_bounds__(256) k_attn()
{
    __shared__ float2 sxr[MPBASE+1];   // up to 139 keys

    const int b  = blockIdx.z;
    const int mp = blockIdx.y;
    const int lb = blockIdx.x*1024 + threadIdx.x;

    const int mstart = part_start(mp);
    const int mlen   = part_len(mp);

    if (threadIdx.x < mlen)
        sxr[threadIdx.x] = ((const float2*)g_xr)[(size_t)b*L_ + mstart + threadIdx.x];

    float al[4], be[4], ga[4];
    #pragma unroll
    for (int j = 0; j < 4; j++) {
        float4 abc = *(const float4*)&g_abc[((size_t)b*L_ + lb + j*256)*4];
        al[j] = abc.x; be[j] = abc.y; ga[j] = abc.z;
    }
    __syncthreads();

    float u0[4], u1[4], u2[4];
    #pragma unroll
    for (int j = 0; j < 4; j++) { u0[j]=0.f; u1[j]=0.f; u2[j]=0.f; }

    #pragma unroll 4
    for (int m = 0; m < mlen; m++) {
        float2 xv = sxr[m];   // broadcast LDS.64
        #pragma unroll
        for (int j = 0; j < 4; j++) {
            float z = fmaf(be[j], xv.x, fmaf(ga[j], xv.y, al[j]));
            float t = ftanh(z);
            u0[j] += t;
            u1[j]  = fmaf(t, xv.x, u1[j]);
            u2[j]  = fmaf(t, xv.y, u2[j]);
        }
    }

    #pragma unroll
    for (int j = 0; j < 4; j++) {
        float4 w; w.x = u0[j]; w.y = u1[j]; w.z = u2[j]; w.w = 0.f;
        *(float4*)&g_part[((size_t)mp*P_ + (size_t)b*L_ + lb + j*256)*4] = w;
    }
}

// ============================================================
// Kernel 4: combine + sigmoid restore + rank-3 V + threshold + fco -> out
// ============================================================
__global__ void __launch_bounds__(256) k_combine(
    const float* __restrict__ fc3_w, const float* __restrict__ fc3_b,
    const float* __restrict__ fco_w, const float* __restrict__ fco_b,
    float* __restrict__ out)
{
    const int idx = blockIdx.x*256 + threadIdx.x;
    const int p   = idx >> 2;
    const int sub = idx & 3;

    float u0=0.f, u1=0.f, u2=0.f;
    for (int s = sub; s < NPART; s += 4) {
        float4 a = *(const float4*)&g_part[((size_t)s*P_ + p)*4];
        u0 += a.x; u1 += a.y; u2 += a.z;
    }
    u0 += __shfl_xor_sync(0xffffffffu, u0, 1);
    u1 += __shfl_xor_sync(0xffffffffu, u1, 1);
    u2 += __shfl_xor_sync(0xffffffffu, u2, 1);
    u0 += __shfl_xor_sync(0xffffffffu, u0, 2);
    u1 += __shfl_xor_sync(0xffffffffu, u1, 2);
    u2 += __shfl_xor_sync(0xffffffffu, u2, 2);

    if (sub == 0) {
        const int b = p / L_;
        float S0 = 0.f, S1 = 0.f;
        #pragma unroll
        for (int s = 0; s < KSLICE; s++) {
            S0 += g_Sp[(b*KSLICE + s)*2];
            S1 += g_Sp[(b*KSLICE + s)*2 + 1];
        }
        const float t0 = 0.5f*(u0 + (float)L_);
        const float t1 = 0.5f*(u1 + S0);
        const float t2 = 0.5f*(u2 + S1);

        float r0 = fco_b[0], r1 = fco_b[1];
        #pragma unroll
        for (int i = 0; i < 8; i++) {
            float o = fmaf(t0, fc3_b[i], fmaf(t1, fc3_w[2*i], t2*fc3_w[2*i+1]));
            o = (o > 0.5f) ? o : 0.f;
            r0 = fmaf(fco_w[i],   o, r0);
            r1 = fmaf(fco_w[8+i], o, r1);
        }
        const int l = p % L_;
        const int t = l / N_;
        const int n = l % N_;
        out[((b*2+0)*T_ + t)*N_ + n] = r0;
        out[((b*2+1)*T_ + t)*N_ + n] = r1;
    }
}

// ============================================================
extern "C" void kernel_launch(void* const* d_in, const int* in_sizes, int n_in,
                              void* d_out, int out_size)
{
    const float* x      = (const float*)d_in[0];
    const float* md     = (const float*)d_in[1];
    const float* w_ih   = (const float*)d_in[2];
    const float* b_ih   = (const float*)d_in[3];
    const float* b_hh   = (const float*)d_in[4];
    const float* comp_w = (const float*)d_in[5];
    const float* comp_b = (const float*)d_in[6];
    const float* vf_w   = (const float*)d_in[7];
    const float* vf_b   = (const float*)d_in[8];
    const float* fc_w   = (const float*)d_in[9];
    const float* fc_b   = (const float*)d_in[10];
    const float* fc2_w  = (const float*)d_in[11];
    const float* fc2_b  = (const float*)d_in[12];
    const float* fc3_w  = (const float*)d_in[13];
    const float* fc3_b  = (const float*)d_in[14];
    const float* fco_w  = (const float*)d_in[15];
    const float* fco_b  = (const float*)d_in[16];
    float* out = (float*)d_out;

    k_compress<<<128, 256>>>(md, comp_w, comp_b, vf_w);
    k_points<<<P_/256, 256>>>(x, w_ih, b_ih, b_hh, vf_w, vf_b,
                              fc_w, fc_b, fc2_w, fc2_b);
    k_keysum<<<B_*KSLICE, 256>>>();
    k_attn<<<dim3(L_/1024, NPART, B_), 256>>>();
    k_combine<<<(P_*4)/256, 256>>>(fc3_w, fc3_b, fco_w, fco_b, out);
}

// round 10
// speedup vs baseline: 1.6020x; 1.0705x over previous
#include <cuda_runtime.h>
#include <math.h>

// ---- problem dims (fixed) ----
#define B_    4
#define T_    20
#define N_    256
#define L_    (T_*N_)    // 5120
#define P_    (B_*L_)    // 20480
#define CMAP_ 2048
#define NPART 37         // 10 l-tiles * 37 * 4 = 1480 = 148 SMs * 10 (2 waves @ occ 5)
#define KSLOT (P_/256)   // 80 per-block keysum slots

typedef unsigned long long ull;

// ---- device scratch ----
__device__ float g_cm4 [4*B_*256*4];
__device__ float g_abc [P_*4];
__device__ float g_xr  [P_*2];
__device__ float g_part[NPART*(size_t)P_*4];
__device__ float g_Sp  [KSLOT*2];    // per-points-block (sum xr0, sum xr1)

// ---- helpers ----
__device__ __forceinline__ ull f2pack(float a, float b){ ull r; asm("mov.b64 %0,{%1,%2};":"=l"(r):"f"(a),"f"(b)); return r; }
__device__ __forceinline__ void f2unpack(ull v, float&a, float&b){ asm("mov.b64 {%0,%1},%2;":"=f"(a),"=f"(b):"l"(v)); }
__device__ __forceinline__ ull f2fma(ull a, ull b, ull c){ ull d; asm("fma.rn.f32x2 %0,%1,%2,%3;":"=l"(d):"l"(a),"l"(b),"l"(c)); return d; }
__device__ __forceinline__ ull f2add(ull a, ull b){ ull d; asm("add.rn.f32x2 %0,%1,%2;":"=l"(d):"l"(a),"l"(b)); return d; }
__device__ __forceinline__ float ftanh(float x){ float r; asm("tanh.approx.f32 %0,%1;":"=f"(r):"f"(x)); return r; }
__device__ __forceinline__ float sigf(float x){ return 1.f/(1.f+expf(-x)); }

// part s: 7 parts of 140 keys then 30 parts of 138 (all even)
__device__ __forceinline__ int part_start(int s){ return 138*s + 2*(s < 7 ? s : 7); }
__device__ __forceinline__ int part_len(int s){ return (s < 7) ? 140 : 138; }

// ============================================================
// Kernel 1: compressor + folded vf projection
// ============================================================
__global__ void __launch_bounds__(256) k_compress(
    const float* __restrict__ md, const float* __restrict__ cw, const float* __restrict__ cb,
    const float* __restrict__ vf_w)
{
    __shared__ float wT[256][36];
    __shared__ float cm32[32][33];

    const int cpart = blockIdx.x & 3;
    const int tile  = (blockIdx.x >> 2) & 7;
    const int b     = blockIdx.x >> 5;
    const int tid  = threadIdx.x;
    const int lane = tid & 31;
    const int warp = tid >> 5;
    const int hw   = tile*32 + lane;

    ull acc[16];
    #pragma unroll
    for (int i=0;i<16;i++) acc[i] = 0ULL;

    #pragma unroll
    for (int chunk = 0; chunk < 2; chunk++) {
        const int cb0 = cpart*512 + chunk*256;
        __syncthreads();
        #pragma unroll 4
        for (int r = 0; r < 32; r++)
            wT[tid][r] = cw[r*CMAP_ + cb0 + tid];
        __syncthreads();

        const int cl0 = warp*32;
        #pragma unroll 4
        for (int k = 0; k < 32; k++) {
            const int cl = cl0 + k;
            float m = md[(size_t)(b*CMAP_ + cb0 + cl)*256 + hw];
            ull m2 = f2pack(m, m);
            const ulonglong2* wrow = (const ulonglong2*)(&wT[cl][0]);
            #pragma unroll
            for (int i = 0; i < 8; i++) {
                ulonglong2 wv = wrow[i];
                acc[2*i]   = f2fma(m2, wv.x, acc[2*i]);
                acc[2*i+1] = f2fma(m2, wv.y, acc[2*i+1]);
            }
        }
    }

    __syncthreads();
    {
        ull* row = (ull*)&wT[tid][0];
        #pragma unroll
        for (int i = 0; i < 16; i++) row[i] = acc[i];
    }
    __syncthreads();

    const int hwl = tid & 31;
    const int og  = tid >> 5;
    float r0=0.f, r1=0.f, r2=0.f, r3=0.f;
    #pragma unroll
    for (int w2 = 0; w2 < 8; w2++) {
        const float* rr = &wT[w2*32 + hwl][og*4];
        r0 += rr[0]; r1 += rr[1]; r2 += rr[2]; r3 += rr[3];
    }
    if (cpart == 0) {
        r0 += cb[og*4+0]; r1 += cb[og*4+1]; r2 += cb[og*4+2]; r3 += cb[og*4+3];
    }
    cm32[hwl][og*4+0] = r0; cm32[hwl][og*4+1] = r1;
    cm32[hwl][og*4+2] = r2; cm32[hwl][og*4+3] = r3;
    __syncthreads();

    if (og < 4) {
        float s = 0.f;
        #pragma unroll
        for (int j = 0; j < 32; j++)
            s = fmaf(vf_w[og*36 + 4 + j], cm32[hwl][j], s);
        g_cm4[(((size_t)cpart*B_ + b)*256 + tile*32 + hwl)*4 + og] = s;
    }
}

// ============================================================
// Kernel 2: per-point prep + per-block keysum partials
// ============================================================
__global__ void __launch_bounds__(256) k_points(
    const float* __restrict__ x,
    const float* __restrict__ w_ih, const float* __restrict__ b_ih, const float* __restrict__ b_hh,
    const float* __restrict__ vf_w, const float* __restrict__ vf_b,
    const float* __restrict__ fc_w, const float* __restrict__ fc_b,
    const float* __restrict__ fc2_w, const float* __restrict__ fc2_b)
{
    __shared__ float r0s[256], r1s[256];

    const int tid = threadIdx.x;
    const int p = blockIdx.x*256 + tid;
    const int b = p / L_;
    const int l = p % L_;
    const int t = l / N_;
    const int n = l % N_;

    const float x0 = x[((b*2+0)*T_ + t)*N_ + n];
    const float x1 = x[((b*2+1)*T_ + t)*N_ + n];
    const float ft = (float)t;
    const float xr0 = x0 + sinf(ft);
    const float xr1 = x1 + cosf(ft);

    float X[4];
    #pragma unroll
    for (int j = 0; j < 4; j++) {
        float ig = fmaf(w_ih[2*j],      xr0, fmaf(w_ih[2*j+1],      xr1, b_ih[j]    + b_hh[j]));
        float gg = fmaf(w_ih[2*(8+j)],  xr0, fmaf(w_ih[2*(8+j)+1],  xr1, b_ih[8+j]  + b_hh[8+j]));
        float og = fmaf(w_ih[2*(12+j)], xr0, fmaf(w_ih[2*(12+j)+1], xr1, b_ih[12+j] + b_hh[12+j]));
        float c  = sigf(ig)*tanhf(gg);
        X[j] = sigf(og)*tanhf(c);
    }

    const float ix = x0*(1.f/32.f) - 0.5f;
    const float iy = x1*(1.f/32.f) - 0.5f;
    const float x0f = floorf(ix), y0f = floorf(iy);
    const float wx1 = ix - x0f, wx0 = 1.f - wx1;
    const float wy1 = iy - y0f, wy0 = 1.f - wy1;
    const int xi0 = (int)x0f, yi0 = (int)y0f;

    float lcp0=0.f, lcp1=0.f, lcp2=0.f, lcp3=0.f;
    #pragma unroll
    for (int cy = 0; cy < 2; cy++) {
        #pragma unroll
        for (int cx = 0; cx < 2; cx++) {
            const int xi = xi0 + cx, yi = yi0 + cy;
            const float wgt = (cx ? wx1 : wx0) * (cy ? wy1 : wy0);
            if (xi >= 0 && xi < 16 && yi >= 0 && yi < 16) {
                #pragma unroll
                for (int part = 0; part < 4; part++) {
                    float4 v = *(const float4*)&g_cm4[(((size_t)part*B_ + b)*256 + yi*16 + xi)*4];
                    lcp0 = fmaf(wgt, v.x, lcp0);
                    lcp1 = fmaf(wgt, v.y, lcp1);
                    lcp2 = fmaf(wgt, v.z, lcp2);
                    lcp3 = fmaf(wgt, v.w, lcp3);
                }
            }
        }
    }

    float X2[4];
    {
        float lcp[4] = {lcp0, lcp1, lcp2, lcp3};
        #pragma unroll
        for (int i = 0; i < 4; i++) {
            float s = vf_b[i] + lcp[i];
            #pragma unroll
            for (int j = 0; j < 4; j++) s = fmaf(vf_w[i*36+j], X[j], s);
            X2[i] = s;
        }
    }

    float alpha = 0.f, beta = 0.f, gamma = 0.f;
    #pragma unroll
    for (int k = 0; k < 8; k++) {
        float q = fc_b[k];
        #pragma unroll
        for (int i = 0; i < 4; i++) q = fmaf(fc_w[k*4+i], X2[i], q);
        alpha = fmaf(q, fc2_b[k],    alpha);
        beta  = fmaf(q, fc2_w[2*k],  beta);
        gamma = fmaf(q, fc2_w[2*k+1],gamma);
    }
    float4 abc; abc.x = alpha*0.5f; abc.y = beta*0.5f; abc.z = gamma*0.5f; abc.w = 0.f;
    *(float4*)&g_abc[(size_t)p*4] = abc;
    float2 xr; xr.x = xr0; xr.y = xr1;
    *(float2*)&g_xr[(size_t)p*2] = xr;

    // per-block keysum partial (deterministic tree)
    r0s[tid] = xr0; r1s[tid] = xr1;
    __syncthreads();
    #pragma unroll
    for (int off = 128; off > 0; off >>= 1) {
        if (tid < off) { r0s[tid] += r0s[tid+off]; r1s[tid] += r1s[tid+off]; }
        __syncthreads();
    }
    if (tid == 0) {
        g_Sp[blockIdx.x*2]     = r0s[0];
        g_Sp[blockIdx.x*2 + 1] = r1s[0];
    }
}

// ============================================================
// Kernel 3: attention partials — f32x2-packed across key pairs
// grid (10 l-tiles, 37 m-parts, 4 batches) = 1480 blocks, 2 q/thread
// ============================================================
__global__ void __launch_bounds__(256, 5) k_attn()
{
    __shared__ float4 sxr[70];   // up to 140 keys as (x0a,x0b,x1a,x1b) pairs

    const int b  = blockIdx.z;
    const int mp = blockIdx.y;
    const int lb = blockIdx.x*512 + threadIdx.x;   // queries lb, lb+256

    const int mstart = part_start(mp);
    const int mh     = part_len(mp) >> 1;          // 69 or 70 key pairs

    if (threadIdx.x < mh) {
        // g_xr float4 covers keys (2i,2i+1) as (x0a,x1a,x0b,x1b) -> swizzle to (x0a,x0b,x1a,x1b)
        float4 v = ((const float4*)g_xr)[(((size_t)b*L_ + mstart) >> 1) + threadIdx.x];
        sxr[threadIdx.x] = make_float4(v.x, v.z, v.y, v.w);
    }

    ull al2[2], be2[2], ga2[2];
    #pragma unroll
    for (int j = 0; j < 2; j++) {
        float4 abc = *(const float4*)&g_abc[((size_t)b*L_ + lb + j*256)*4];
        al2[j] = f2pack(abc.x, abc.x);
        be2[j] = f2pack(abc.y, abc.y);
        ga2[j] = f2pack(abc.z, abc.z);
    }
    __syncthreads();

    ull u0[2], u1[2], u2[2];
    #pragma unroll
    for (int j = 0; j < 2; j++) { u0[j]=0ULL; u1[j]=0ULL; u2[j]=0ULL; }

    const ulonglong2* kvp = (const ulonglong2*)sxr;

    #pragma unroll 2
    for (int m = 0; m < mh; m++) {
        ulonglong2 xv = kvp[m];   // xv.x = (x0a,x0b), xv.y = (x1a,x1b) — broadcast LDS.128
        #pragma unroll
        for (int j = 0; j < 2; j++) {
            ull z2 = f2fma(be2[j], xv.x, f2fma(ga2[j], xv.y, al2[j]));
            float za, zb; f2unpack(z2, za, zb);
            float ta = ftanh(za);
            float tb = ftanh(zb);
            ull tp = f2pack(ta, tb);
            u0[j] = f2add(u0[j], tp);
            u1[j] = f2fma(tp, xv.x, u1[j]);
            u2[j] = f2fma(tp, xv.y, u2[j]);
        }
    }

    #pragma unroll
    for (int j = 0; j < 2; j++) {
        float a, bb, c, d, e, f;
        f2unpack(u0[j], a, bb);
        f2unpack(u1[j], c, d);
        f2unpack(u2[j], e, f);
        float4 w; w.x = a + bb; w.y = c + d; w.z = e + f; w.w = 0.f;
        *(float4*)&g_part[((size_t)mp*P_ + (size_t)b*L_ + lb + j*256)*4] = w;
    }
}

// ============================================================
// Kernel 4: combine + sigmoid restore + rank-3 V + threshold + fco -> out
// ============================================================
__global__ void __launch_bounds__(256) k_combine(
    const float* __restrict__ fc3_w, const float* __restrict__ fc3_b,
    const float* __restrict__ fco_w, const float* __restrict__ fco_b,
    float* __restrict__ out)
{
    const int idx = blockIdx.x*256 + threadIdx.x;
    const int p   = idx >> 2;
    const int sub = idx & 3;

    float u0=0.f, u1=0.f, u2=0.f;
    for (int s = sub; s < NPART; s += 4) {
        float4 a = *(const float4*)&g_part[((size_t)s*P_ + p)*4];
        u0 += a.x; u1 += a.y; u2 += a.z;
    }
    u0 += __shfl_xor_sync(0xffffffffu, u0, 1);
    u1 += __shfl_xor_sync(0xffffffffu, u1, 1);
    u2 += __shfl_xor_sync(0xffffffffu, u2, 1);
    u0 += __shfl_xor_sync(0xffffffffu, u0, 2);
    u1 += __shfl_xor_sync(0xffffffffu, u1, 2);
    u2 += __shfl_xor_sync(0xffffffffu, u2, 2);

    if (sub == 0) {
        const int b = p / L_;
        float S0 = 0.f, S1 = 0.f;
        #pragma unroll
        for (int s = 0; s < 20; s++) {   // 20 points-blocks per batch
            S0 += g_Sp[(b*20 + s)*2];
            S1 += g_Sp[(b*20 + s)*2 + 1];
        }
        const float t0 = 0.5f*(u0 + (float)L_);
        const float t1 = 0.5f*(u1 + S0);
        const float t2 = 0.5f*(u2 + S1);

        float r0 = fco_b[0], r1 = fco_b[1];
        #pragma unroll
        for (int i = 0; i < 8; i++) {
            float o = fmaf(t0, fc3_b[i], fmaf(t1, fc3_w[2*i], t2*fc3_w[2*i+1]));
            o = (o > 0.5f) ? o : 0.f;
            r0 = fmaf(fco_w[i],   o, r0);
            r1 = fmaf(fco_w[8+i], o, r1);
        }
        const int l = p % L_;
        const int t = l / N_;
        const int n = l % N_;
        out[((b*2+0)*T_ + t)*N_ + n] = r0;
        out[((b*2+1)*T_ + t)*N_ + n] = r1;
    }
}

// ============================================================
extern "C" void kernel_launch(void* const* d_in, const int* in_sizes, int n_in,
                              void* d_out, int out_size)
{
    const float* x      = (const float*)d_in[0];
    const float* md     = (const float*)d_in[1];
    const float* w_ih   = (const float*)d_in[2];
    const float* b_ih   = (const float*)d_in[3];
    const float* b_hh   = (const float*)d_in[4];
    const float* comp_w = (const float*)d_in[5];
    const float* comp_b = (const float*)d_in[6];
    const float* vf_w   = (const float*)d_in[7];
    const float* vf_b   = (const float*)d_in[8];
    const float* fc_w   = (const float*)d_in[9];
    const float* fc_b   = (const float*)d_in[10];
    const float* fc2_w  = (const float*)d_in[11];
    const float* fc2_b  = (const float*)d_in[12];
    const float* fc3_w  = (const float*)d_in[13];
    const float* fc3_b  = (const float*)d_in[14];
    const float* fco_w  = (const float*)d_in[15];
    const float* fco_b  = (const float*)d_in[16];
    float* out = (float*)d_out;

    k_compress<<<128, 256>>>(md, comp_w, comp_b, vf_w);
    k_points<<<P_/256, 256>>>(x, w_ih, b_ih, b_hh, vf_w, vf_b,
                              fc_w, fc_b, fc2_w, fc2_b);
    k_attn<<<dim3(L_/512, NPART, B_), 256>>>();
    k_combine<<<(P_*4)/256, 256>>>(fc3_w, fc3_b, fco_w, fco_b, out);
}